// round 12
// baseline (speedup 1.0000x reference)
#include <cuda_runtime.h>
#include <cuda_bf16.h>
#include <cuda_fp16.h>
#include <cstdint>

// Problem dims
#define NB 65536
#define NBH (NB / 2)
#define NC 1024
#define ND 256
#define NK 2048
#define NCB 4

// Output layout (float32): [z_q][vq_loss][enc_loss][cbk_loss][codes][latents]
#define O_SC   (NB * NC)
#define O_CODE (O_SC + 3)
#define O_LAT  (O_CODE + NB * NCB)
#define O_TOT  (O_LAT + NB * NCB * ND)

// Scratch
__device__ float g_res[NB * NC];            // residual (256 MB)
__device__ float g_ze[NB * ND];             // z_e (64 MB)
__device__ float g_zqst[NB * ND];           // straight-through (64 MB)
__device__ __half g_dot[(size_t)NB * NK];   // fp16 tensor dots (256 MB)
__device__ float g_cbn[NCB * NK];           // per-codebook ||cb_k||^2
__device__ float g_zn[NB];
__device__ int   g_idx[NB];
__device__ float g_rowloss[NB];

// bf16x2 pack: element order [a, b]
__device__ __forceinline__ uint32_t pack_bf16x2(float a, float b) {
    uint32_t r;
    asm("cvt.rn.satfinite.bf16x2.f32 %0, %1, %2;" : "=r"(r) : "f"(b), "f"(a));
    return r;
}

// ===========================================================================
// fp32 SIMT GEMM body (bit-identical arithmetic to passing rounds)
#define GEMM_BODY(A_, B_, K_, N_) \
    const int BM = 128, BN = 64, BK = 16, TM = 8, TN = 4; \
    __shared__ float As[BK][BM + 4]; \
    __shared__ float Bs[BK][BN]; \
    int tid = threadIdx.x; \
    int tx = tid & 15; \
    int ty = tid >> 4; \
    int row0 = blockIdx.y * BM + rbase; \
    int col0 = blockIdx.x * BN; \
    float acc[TM][TN]; \
    _Pragma("unroll") for (int m = 0; m < TM; m++) \
        _Pragma("unroll") for (int n = 0; n < TN; n++) acc[m][n] = 0.0f; \
    for (int k0 = 0; k0 < (K_); k0 += BK) { \
        _Pragma("unroll") for (int i = 0; i < 2; i++) { \
            int f4 = i * 256 + tid; \
            int r = f4 >> 2, c4 = f4 & 3; \
            float4 v = *(const float4*)&(A_)[(long)(row0 + r) * (K_) + k0 + c4 * 4]; \
            As[c4 * 4 + 0][r] = v.x; As[c4 * 4 + 1][r] = v.y; \
            As[c4 * 4 + 2][r] = v.z; As[c4 * 4 + 3][r] = v.w; \
        } \
        { \
            int r = tid >> 4, c4 = tid & 15; \
            float4 v = *(const float4*)&(B_)[(long)(k0 + r) * (N_) + col0 + c4 * 4]; \
            *(float4*)&Bs[r][c4 * 4] = v; \
        } \
        __syncthreads(); \
        _Pragma("unroll") for (int kk = 0; kk < BK; kk++) { \
            float a[TM], b[TN]; \
            float4 a0 = *(const float4*)&As[kk][ty * TM]; \
            float4 a1 = *(const float4*)&As[kk][ty * TM + 4]; \
            a[0]=a0.x; a[1]=a0.y; a[2]=a0.z; a[3]=a0.w; \
            a[4]=a1.x; a[5]=a1.y; a[6]=a1.z; a[7]=a1.w; \
            float4 b0 = *(const float4*)&Bs[kk][tx * TN]; \
            b[0]=b0.x; b[1]=b0.y; b[2]=b0.z; b[3]=b0.w; \
            _Pragma("unroll") for (int m = 0; m < TM; m++) \
                _Pragma("unroll") for (int n = 0; n < TN; n++) \
                    acc[m][n] = fmaf(a[m], b[n], acc[m][n]); \
        } \
        __syncthreads(); \
    }

// z_e = A @ W_in + b_in
__global__ void __launch_bounds__(256) k_gemm_ze(
    const float* __restrict__ A, const float* __restrict__ Bm,
    const float* __restrict__ bias, float* __restrict__ C,
    int K_, int N_, int rbase)
{
    GEMM_BODY(A, Bm, K_, N_)
#pragma unroll
    for (int m = 0; m < TM; m++) {
        long orow = row0 + ty * TM + m;
#pragma unroll
        for (int n = 0; n < TN; n++) {
            int oc = col0 + tx * TN + n;
            C[orow * N_ + oc] = __fadd_rn(acc[m][n], bias[oc]);
        }
    }
}

// z_q_i = z_q_st @ W_out + b_out, fused apply
__global__ void __launch_bounds__(256) k_gemm_out(
    const float* __restrict__ A, const float* __restrict__ Bm,
    const float* __restrict__ bias, float* __restrict__ zq,
    const float* __restrict__ z, int K_, int N_, int cbi, int rbase)
{
    GEMM_BODY(A, Bm, K_, N_)
#pragma unroll
    for (int m = 0; m < TM; m++) {
        long orow = row0 + ty * TM + m;
#pragma unroll
        for (int n = 0; n < TN; n++) {
            int oc = col0 + tx * TN + n;
            long off = orow * N_ + oc;
            float qi = __fadd_rn(acc[m][n], bias[oc]);
            if (cbi == 0) {
                g_res[off] = __fsub_rn(z[off], qi);
                zq[off] = qi;
            } else if (cbi < NCB - 1) {
                g_res[off] = __fsub_rn(g_res[off], qi);
                zq[off] = __fadd_rn(zq[off], qi);
            } else {
                zq[off] = __fadd_rn(zq[off], qi);
            }
        }
    }
}

// ===========================================================================
__device__ __forceinline__ float row_sumsq_vec4(const float* __restrict__ row) {
    int l = threadIdx.x & 31;
    float4 a = *(const float4*)&row[4 * l];
    float4 b = *(const float4*)&row[128 + 4 * l];
    float s;
    s = __fmul_rn(a.x, a.x);
    s = __fadd_rn(s, __fmul_rn(a.y, a.y));
    s = __fadd_rn(s, __fmul_rn(a.z, a.z));
    s = __fadd_rn(s, __fmul_rn(a.w, a.w));
    s = __fadd_rn(s, __fmul_rn(b.x, b.x));
    s = __fadd_rn(s, __fmul_rn(b.y, b.y));
    s = __fadd_rn(s, __fmul_rn(b.z, b.z));
    s = __fadd_rn(s, __fmul_rn(b.w, b.w));
#pragma unroll
    for (int off = 16; off > 0; off >>= 1)
        s = __fadd_rn(s, __shfl_down_sync(0xffffffffu, s, off));
    return s;
}

__global__ void k_cbn(const float* __restrict__ cb, int cbi) {
    int w = threadIdx.x >> 5;
    int k = blockIdx.x * 4 + w;
    float s = row_sumsq_vec4(cb + (long)k * ND);
    if ((threadIdx.x & 31) == 0) g_cbn[cbi * NK + k] = s;
}
__global__ void k_rownorm(int rbase) {
    int w = threadIdx.x >> 5;
    int b = blockIdx.x * 4 + w + rbase;
    float s = row_sumsq_vec4(g_ze + (long)b * ND);
    if ((threadIdx.x & 31) == 0) g_zn[b] = s;
}

// ===========================================================================
// bf16 mma.sync dot GEMM (fp16 store)
#define ASTRIDE 264
#define DOT_SMEM_B (128 * ASTRIDE * 2)
#define DOT_SMEM_TOTAL (DOT_SMEM_B + 64 * ASTRIDE * 2)

__device__ __forceinline__ void mma16816(float* c, uint32_t a0, uint32_t a1,
                                         uint32_t a2, uint32_t a3,
                                         uint32_t b0, uint32_t b1) {
    asm volatile(
        "mma.sync.aligned.m16n8k16.row.col.f32.bf16.bf16.f32 "
        "{%0,%1,%2,%3}, {%4,%5,%6,%7}, {%8,%9}, {%0,%1,%2,%3};"
        : "+f"(c[0]), "+f"(c[1]), "+f"(c[2]), "+f"(c[3])
        : "r"(a0), "r"(a1), "r"(a2), "r"(a3), "r"(b0), "r"(b1));
}

__global__ void __launch_bounds__(256) k_dots(const float* __restrict__ cb, int rbase) {
    extern __shared__ char smem[];
    __nv_bfloat16* As = (__nv_bfloat16*)(smem);
    __nv_bfloat16* Bs = (__nv_bfloat16*)(smem + DOT_SMEM_B);
    int tid = threadIdx.x;
    int wid = tid >> 5, lane = tid & 31;
    int gid = lane >> 2, tig = lane & 3;
    int row0 = blockIdx.x * 128 + rbase;

    for (int i = tid; i < 128 * 64; i += 256) {
        int r = i >> 6;
        int c = (i & 63) * 4;
        float4 v = *(const float4*)&g_ze[(long)(row0 + r) * ND + c];
        uint2 p = make_uint2(pack_bf16x2(v.x, v.y), pack_bf16x2(v.z, v.w));
        *(uint2*)&As[r * ASTRIDE + c] = p;
    }

    for (int chunk = 0; chunk < 32; chunk++) {
        int n0 = chunk * 64;
        for (int i = tid; i < 64 * 64; i += 256) {
            int r = i >> 6;
            int c = (i & 63) * 4;
            float4 v = *(const float4*)&cb[(long)(n0 + r) * ND + c];
            uint2 p = make_uint2(pack_bf16x2(v.x, v.y), pack_bf16x2(v.z, v.w));
            *(uint2*)&Bs[r * ASTRIDE + c] = p;
        }
        __syncthreads();

        float acc[8][4];
#pragma unroll
        for (int n8 = 0; n8 < 8; n8++)
#pragma unroll
            for (int j = 0; j < 4; j++) acc[n8][j] = 0.0f;

        int arow = wid * 16 + gid;
#pragma unroll
        for (int ks = 0; ks < 16; ks++) {
            int ak = ks * 16 + tig * 2;
            uint32_t a0 = *(const uint32_t*)&As[arow * ASTRIDE + ak];
            uint32_t a1 = *(const uint32_t*)&As[(arow + 8) * ASTRIDE + ak];
            uint32_t a2 = *(const uint32_t*)&As[arow * ASTRIDE + ak + 8];
            uint32_t a3 = *(const uint32_t*)&As[(arow + 8) * ASTRIDE + ak + 8];
#pragma unroll
            for (int n8 = 0; n8 < 8; n8++) {
                int brow = n8 * 8 + gid;
                uint32_t b0 = *(const uint32_t*)&Bs[brow * ASTRIDE + ak];
                uint32_t b1 = *(const uint32_t*)&Bs[brow * ASTRIDE + ak + 8];
                mma16816(acc[n8], a0, a1, a2, a3, b0, b1);
            }
        }

        size_t rbase0 = (size_t)(row0 + wid * 16 + gid) * NK + n0;
        size_t rbase1 = rbase0 + (size_t)8 * NK;
#pragma unroll
        for (int n8 = 0; n8 < 8; n8++) {
            int col = n8 * 8 + tig * 2;
            *(__half2*)&g_dot[rbase0 + col] = __floats2half2_rn(acc[n8][0], acc[n8][1]);
            *(__half2*)&g_dot[rbase1 + col] = __floats2half2_rn(acc[n8][2], acc[n8][3]);
        }
        __syncthreads();
    }
}

// ===========================================================================
#define MARGIN 0.12f
__global__ void __launch_bounds__(256) k_argsel(const float* __restrict__ cb,
                                                int cbi, int rbase) {
    int w = threadIdx.x >> 5, l = threadIdx.x & 31;
    int row = blockIdx.x * 8 + w + rbase;
    const __half2* drow = (const __half2*)&g_dot[(size_t)row * NK];
    const float* cbn = &g_cbn[cbi * NK];
    float zn = g_zn[row];

    float dmin = 3.4e38f;
#pragma unroll 4
    for (int j = 0; j < NK / 64; j++) {
        int kh = j * 32 + l;
        float2 dd = __half22float2(drow[kh]);
        float da0 = zn - 2.0f * dd.x + cbn[2 * kh];
        float da1 = zn - 2.0f * dd.y + cbn[2 * kh + 1];
        dmin = fminf(dmin, fminf(da0, da1));
    }
#pragma unroll
    for (int off = 16; off > 0; off >>= 1)
        dmin = fminf(dmin, __shfl_xor_sync(0xffffffffu, dmin, off));
    float thr = dmin + MARGIN;

    float best = 3.4e38f;
    int bidx = 0x40000000;
    const float* ze = &g_ze[(long)row * ND];
    for (int j = 0; j < NK / 64; j++) {
        int kh = j * 32 + l;
        float2 dd = __half22float2(drow[kh]);
#pragma unroll
        for (int h = 0; h < 2; h++) {
            int k = 2 * kh + h;
            float da = zn - 2.0f * (h ? dd.y : dd.x) + cbn[k];
            if (da <= thr) {
                const float* cr = &cb[(long)k * ND];
                float acc = 0.0f;
#pragma unroll 8
                for (int t = 0; t < ND; t++) acc = fmaf(ze[t], cr[t], acc);
                float de = __fadd_rn(__fsub_rn(zn, __fmul_rn(2.0f, acc)), cbn[k]);
                if (de < best || (de == best && k < bidx)) { best = de; bidx = k; }
            }
        }
    }
#pragma unroll
    for (int off = 16; off > 0; off >>= 1) {
        float ov = __shfl_down_sync(0xffffffffu, best, off);
        int   oi = __shfl_down_sync(0xffffffffu, bidx, off);
        if (ov < best || (ov == best && oi < bidx)) { best = ov; bidx = oi; }
    }
    if (l == 0) g_idx[row] = bidx;
}

// ===========================================================================
__global__ void k_gather(const float* __restrict__ cb, float* __restrict__ out,
                         int cbi, int writeFull, int rbase) {
    int b = blockIdx.x + rbase;
    int t = threadIdx.x;
    int idx = g_idx[b];

    float ze = g_ze[(long)b * ND + t];
    float cv = cb[(long)idx * ND + t];
    g_zqst[(long)b * ND + t] = __fadd_rn(ze, __fsub_rn(cv, ze));

    float df = ze - cv;
    float s = df * df;
#pragma unroll
    for (int off = 16; off > 0; off >>= 1) s += __shfl_down_sync(0xffffffffu, s, off);
    __shared__ float ws[8];
    if ((t & 31) == 0) ws[t >> 5] = s;
    __syncthreads();
    if (t == 0) {
        float tot = 0.0f;
#pragma unroll
        for (int w = 0; w < 8; w++) tot += ws[w];
        g_rowloss[b] = (cbi == 0) ? tot : (g_rowloss[b] + tot);
    }

    if (writeFull) {
        out[O_LAT + (long)b * NC + cbi * ND + t] = ze;
        if (t == 0) out[O_CODE + (long)b * NCB + cbi] = (float)idx;
    }
}

// ===========================================================================
__global__ void k_loss(float* __restrict__ out, int writeFull) {
    __shared__ float sm[1024];
    int t = threadIdx.x;
    float s = 0.0f;
    for (int i = t; i < NB; i += 1024) s += g_rowloss[i];
    sm[t] = s;
    __syncthreads();
    for (int off = 512; off > 0; off >>= 1) {
        if (t < off) sm[t] += sm[t + off];
        __syncthreads();
    }
    if (t == 0 && writeFull) {
        float enc = 0.25f * sm[0] / 16777216.0f;
        out[O_SC + 0] = enc;
        out[O_SC + 1] = enc;
        out[O_SC + 2] = 0.0f;
    }
}

// ===========================================================================
extern "C" void kernel_launch(void* const* d_in, const int* in_sizes, int n_in,
                              void* d_out, int out_size) {
    const float* z   = (const float*)d_in[0];
    const float* cbs = (const float*)d_in[1];
    const float* Wi  = (const float*)d_in[2];
    const float* bi  = (const float*)d_in[3];
    const float* Wo  = (const float*)d_in[4];
    const float* bo  = (const float*)d_in[5];
    float* out = (float*)d_out;
    int writeFull = (out_size >= O_TOT) ? 1 : 0;

    // One-time host resources
    static cudaStream_t s1 = nullptr;
    static cudaEvent_t evG[4 * NCB];   // one per GEMM in the global zipper order
    static cudaEvent_t evJoin = nullptr;
    if (s1 == nullptr) {
        cudaStreamCreateWithFlags(&s1, cudaStreamNonBlocking);
        for (int i = 0; i < 4 * NCB; i++)
            cudaEventCreateWithFlags(&evG[i], cudaEventDisableTiming);
        cudaEventCreateWithFlags(&evJoin, cudaEventDisableTiming);
        cudaFuncSetAttribute(k_dots, cudaFuncAttributeMaxDynamicSharedMemorySize, DOT_SMEM_TOTAL);
    }

    float *p_res, *p_ze, *p_zqst;
    cudaGetSymbolAddress((void**)&p_res,  g_res);
    cudaGetSymbolAddress((void**)&p_ze,   g_ze);
    cudaGetSymbolAddress((void**)&p_zqst, g_zqst);

    // Codebook norms upfront (stream 0; A_ze0's event transitively covers them for s1).
    for (int i = 0; i < NCB; i++)
        k_cbn<<<NK / 4, 128>>>(cbs + (long)i * NK * ND, i);

    // GEMM zipper: global order A_ze_i, B_ze_i, A_out_i, B_out_i; each GEMM
    // waits the previous zipper GEMM (cross-stream) so GEMMs run back-to-back
    // on the FMA pipe while each stream's non-GEMM work hides under the other
    // stream's GEMM window.
    int p = 0;
    for (int i = 0; i < NCB; i++) {
        const float* cb = cbs + (long)i * NK * ND;
        const float* WiP = Wi + (long)i * NC * ND;
        const float* WoP = Wo + (long)i * ND * NC;
        const float* biP = bi + i * ND;
        const float* boP = bo + i * NC;

        // --- A: ze_i (stream 0, rows [0, NBH)) ---
        if (p > 0) cudaStreamWaitEvent(0, evG[p - 1], 0);
        k_gemm_ze<<<dim3(ND / 64, NBH / 128), 256, 0, 0>>>(
            (i == 0) ? z : p_res, WiP, biP, p_ze, NC, ND, 0);
        cudaEventRecord(evG[p], 0); p++;
        // A non-GEMM i
        k_rownorm<<<NBH / 4, 128, 0, 0>>>(0);
        k_dots<<<NBH / 128, 256, DOT_SMEM_TOTAL, 0>>>(cb, 0);
        k_argsel<<<NBH / 8, 256, 0, 0>>>(cb, i, 0);
        k_gather<<<NBH, 256, 0, 0>>>(cb, out, i, writeFull, 0);

        // --- B: ze_i (stream s1, rows [NBH, NB)) ---
        cudaStreamWaitEvent(s1, evG[p - 1], 0);
        k_gemm_ze<<<dim3(ND / 64, NBH / 128), 256, 0, s1>>>(
            (i == 0) ? z : p_res, WiP, biP, p_ze, NC, ND, NBH);
        cudaEventRecord(evG[p], s1); p++;
        // B non-GEMM i
        k_rownorm<<<NBH / 4, 128, 0, s1>>>(NBH);
        k_dots<<<NBH / 128, 256, DOT_SMEM_TOTAL, s1>>>(cb, NBH);
        k_argsel<<<NBH / 8, 256, 0, s1>>>(cb, i, NBH);
        k_gather<<<NBH, 256, 0, s1>>>(cb, out, i, writeFull, NBH);

        // --- A: out_i ---
        cudaStreamWaitEvent(0, evG[p - 1], 0);
        k_gemm_out<<<dim3(NC / 64, NBH / 128), 256, 0, 0>>>(
            p_zqst, WoP, boP, out, z, ND, NC, i, 0);
        cudaEventRecord(evG[p], 0); p++;

        // --- B: out_i ---
        cudaStreamWaitEvent(s1, evG[p - 1], 0);
        k_gemm_out<<<dim3(NC / 64, NBH / 128), 256, 0, s1>>>(
            p_zqst, WoP, boP, out, z, ND, NC, i, NBH);
        cudaEventRecord(evG[p], s1); p++;
    }

    // Join: stream 0 waits for B's tail, then the loss reduction.
    cudaEventRecord(evJoin, s1);
    cudaStreamWaitEvent(0, evJoin, 0);
    k_loss<<<1, 1024>>>(out, writeFull);
}